// round 3
// baseline (speedup 1.0000x reference)
#include <cuda_runtime.h>
#include <math.h>

#define B_  2
#define L_  2048
#define C_  1024
#define H_  16
#define HD_ 64
#define M_  (B_*L_)      // 4096
#define NQKV_ (3*C_)     // 3072

// Scratch (allocation-free rule: device globals)
__device__ float g_q [B_*H_*L_*HD_];   // [B,H,L,HD]
__device__ float g_k [B_*H_*L_*HD_];
__device__ float g_v [B_*H_*L_*HD_];
__device__ float g_ao[B_*L_*C_];       // attention output [B,L,C]

// ---------------------------------------------------------------------------
// GEMM: out[m,n] = sum_k A[m,k] * W[n,k]   (A:[M,1024] row-major, W:[N,1024] row-major)
// BM=BN=128, BK=8, 256 threads, 8x8 per-thread tile, double-buffered smem.
// MODE 0: qkv epilogue (scatter to g_q/g_k/g_v with q_bias / 0 / v_bias)
// MODE 1: proj epilogue (A is g_ao, add b_proj, write d_out)
// ---------------------------------------------------------------------------
template<int MODE>
__global__ __launch_bounds__(256) void gemm_kernel(
    const float* __restrict__ Ain,
    const float* __restrict__ W,
    const float* __restrict__ bias0,   // q_bias (mode0) / b_proj (mode1)
    const float* __restrict__ bias1,   // v_bias (mode0) / unused
    float* __restrict__ out)           // unused (mode0) / d_out (mode1)
{
    __shared__ float As[2][8][132];
    __shared__ float Ws[2][8][132];

    const int K = 1024;
    const int NKT = K / 8;             // 128 k-tiles

    const float* A = (MODE == 1) ? (const float*)g_ao : Ain;

    const int tid = threadIdx.x;
    const int tx  = tid & 15;
    const int ty  = tid >> 4;
    const int m0  = blockIdx.y * 128;
    const int n0  = blockIdx.x * 128;

    const int lrow = tid >> 1;         // 0..127
    const int lkg  = (tid & 1) * 4;    // 0 or 4

    const float* Ap = A + (size_t)(m0 + lrow) * K + lkg;
    const float* Wp = W + (size_t)(n0 + lrow) * K + lkg;

    float acc[8][8];
    #pragma unroll
    for (int i = 0; i < 8; i++)
        #pragma unroll
        for (int j = 0; j < 8; j++) acc[i][j] = 0.f;

    float (*cA)[132] = As[0];
    float (*cW)[132] = Ws[0];
    float (*nA)[132] = As[1];
    float (*nW)[132] = Ws[1];

    // preload tile 0
    {
        float4 av = *(const float4*)(Ap);
        float4 wv = *(const float4*)(Wp);
        cA[lkg+0][lrow] = av.x; cA[lkg+1][lrow] = av.y;
        cA[lkg+2][lrow] = av.z; cA[lkg+3][lrow] = av.w;
        cW[lkg+0][lrow] = wv.x; cW[lkg+1][lrow] = wv.y;
        cW[lkg+2][lrow] = wv.z; cW[lkg+3][lrow] = wv.w;
    }
    __syncthreads();

    for (int kt = 0; kt < NKT; kt++) {
        float4 av, wv;
        const bool has_next = (kt + 1 < NKT);
        if (has_next) {
            av = *(const float4*)(Ap + (kt + 1) * 8);
            wv = *(const float4*)(Wp + (kt + 1) * 8);
        }

        #pragma unroll
        for (int kk = 0; kk < 8; kk++) {
            float fa[8], fb[8];
            *(float4*)&fa[0] = *(float4*)&cA[kk][ty*8];
            *(float4*)&fa[4] = *(float4*)&cA[kk][ty*8+4];
            *(float4*)&fb[0] = *(float4*)&cW[kk][tx*8];
            *(float4*)&fb[4] = *(float4*)&cW[kk][tx*8+4];
            #pragma unroll
            for (int i = 0; i < 8; i++)
                #pragma unroll
                for (int j = 0; j < 8; j++)
                    acc[i][j] += fa[i] * fb[j];
        }

        if (has_next) {
            nA[lkg+0][lrow] = av.x; nA[lkg+1][lrow] = av.y;
            nA[lkg+2][lrow] = av.z; nA[lkg+3][lrow] = av.w;
            nW[lkg+0][lrow] = wv.x; nW[lkg+1][lrow] = wv.y;
            nW[lkg+2][lrow] = wv.z; nW[lkg+3][lrow] = wv.w;
            __syncthreads();
            float (*t)[132];
            t = cA; cA = nA; nA = t;
            t = cW; cW = nW; nW = t;
        }
    }

    // ----- epilogue -----
    #pragma unroll
    for (int i = 0; i < 8; i++) {
        const int m = m0 + ty * 8 + i;
        if (MODE == 0) {
            const int b = m >> 11;        // m / L_
            const int l = m & 2047;
            #pragma unroll
            for (int jv = 0; jv < 8; jv += 4) {
                const int n     = n0 + tx * 8 + jv;
                const int which = n >> 10;          // 0=q 1=k 2=v
                const int rem   = n & 1023;
                const int h     = rem >> 6;
                const int hd    = rem & 63;
                float4 o;
                o.x = acc[i][jv+0]; o.y = acc[i][jv+1];
                o.z = acc[i][jv+2]; o.w = acc[i][jv+3];
                if (which == 0) {
                    o.x += bias0[rem+0]; o.y += bias0[rem+1];
                    o.z += bias0[rem+2]; o.w += bias0[rem+3];
                } else if (which == 2) {
                    o.x += bias1[rem+0]; o.y += bias1[rem+1];
                    o.z += bias1[rem+2]; o.w += bias1[rem+3];
                }
                float* dst = (which == 0) ? g_q : (which == 1) ? g_k : g_v;
                *(float4*)&dst[(((size_t)(b * H_ + h)) * L_ + l) * HD_ + hd] = o;
            }
        } else {
            #pragma unroll
            for (int jv = 0; jv < 8; jv += 4) {
                const int n = n0 + tx * 8 + jv;
                float4 o;
                o.x = acc[i][jv+0] + bias0[n+0];
                o.y = acc[i][jv+1] + bias0[n+1];
                o.z = acc[i][jv+2] + bias0[n+2];
                o.w = acc[i][jv+3] + bias0[n+3];
                *(float4*)&out[(size_t)m * C_ + n] = o;
            }
        }
    }
}

// ---------------------------------------------------------------------------
// L2-normalize q (×exp(min(scale_mul,log100))) and k. One warp per 64-elem row.
// ---------------------------------------------------------------------------
__global__ __launch_bounds__(256) void norm_kernel(const float* __restrict__ scale_mul)
{
    const int row  = blockIdx.x * 8 + (threadIdx.x >> 5);   // 0 .. 2*B*H*L-1
    const int lane = threadIdx.x & 31;
    const int NROW = B_ * H_ * L_;                          // 65536
    float* base = (row < NROW) ? (g_q + (size_t)row * HD_)
                               : (g_k + (size_t)(row - NROW) * HD_);
    float2 v = *(float2*)(base + lane * 2);
    float ss = v.x * v.x + v.y * v.y;
    #pragma unroll
    for (int off = 16; off; off >>= 1)
        ss += __shfl_xor_sync(0xffffffffu, ss, off, 32);
    float s = rsqrtf(ss);
    if (row < NROW) {
        const int h = (row >> 11) & 15;
        s *= __expf(fminf(scale_mul[h], 4.6051702f));  // log(100)
    }
    v.x *= s; v.y *= s;
    *(float2*)(base + lane * 2) = v;
}

// ---------------------------------------------------------------------------
// Fused flash attention. Block = (q-tile of 64 rows) x (one b,h).
// 256 threads as 16x16: thread(ty,tx) owns S rows 4ty+i, S cols tx+16j,
// O cols 4tx+dd. Online softmax with width-16 shuffle reductions.
// ---------------------------------------------------------------------------
__global__ __launch_bounds__(256) void attn_kernel(const float* __restrict__ bias)
{
    extern __shared__ float smem[];
    float* Qs = smem;               // [64][68]
    float* Ks = Qs + 64 * 68;       // [64][68]
    float* Vs = Ks + 64 * 68;       // [64][68]
    float* Ps = Vs + 64 * 68;       // [64][64]

    const int tid = threadIdx.x;
    const int tx  = tid & 15;
    const int ty  = tid >> 4;
    const int bh  = blockIdx.y;              // b*H + h
    const int q0  = blockIdx.x * 64;

    const float* qp    = g_q + ((size_t)bh * L_ + q0) * HD_;
    const float* kbase = g_k + (size_t)bh * L_ * HD_;
    const float* vbase = g_v + (size_t)bh * L_ * HD_;

    // load Q tile (coalesced)
    #pragma unroll
    for (int it = 0; it < 4; it++) {
        const int idx = tid + it * 256;
        const int r = idx >> 4, dg = (idx & 15) * 4;
        *(float4*)&Qs[r * 68 + dg] = *(const float4*)(qp + r * HD_ + dg);
    }

    float m_i[4], l_i[4], O[4][4];
    #pragma unroll
    for (int i = 0; i < 4; i++) {
        m_i[i] = -1e30f; l_i[i] = 0.f;
        #pragma unroll
        for (int d = 0; d < 4; d++) O[i][d] = 0.f;
    }

    for (int k0 = 0; k0 < L_; k0 += 64) {
        __syncthreads();   // protect Ks/Vs/Ps reuse from previous chunk
        #pragma unroll
        for (int it = 0; it < 4; it++) {
            const int idx = tid + it * 256;
            const int r = idx >> 4, dg = (idx & 15) * 4;
            *(float4*)&Ks[r * 68 + dg] = *(const float4*)(kbase + (size_t)(k0 + r) * HD_ + dg);
            *(float4*)&Vs[r * 68 + dg] = *(const float4*)(vbase + (size_t)(k0 + r) * HD_ + dg);
        }
        __syncthreads();

        // S = Q @ K^T  (4x4 per thread)
        float s[4][4];
        #pragma unroll
        for (int i = 0; i < 4; i++)
            #pragma unroll
            for (int j = 0; j < 4; j++) s[i][j] = 0.f;

        #pragma unroll 4
        for (int d = 0; d < 64; d += 4) {
            float qf[4][4], kf[4][4];
            #pragma unroll
            for (int i = 0; i < 4; i++)
                *(float4*)qf[i] = *(float4*)&Qs[(4 * ty + i) * 68 + d];
            #pragma unroll
            for (int j = 0; j < 4; j++)
                *(float4*)kf[j] = *(float4*)&Ks[(tx + 16 * j) * 68 + d];
            #pragma unroll
            for (int i = 0; i < 4; i++)
                #pragma unroll
                for (int j = 0; j < 4; j++) {
                    s[i][j] += qf[i][0] * kf[j][0];
                    s[i][j] += qf[i][1] * kf[j][1];
                    s[i][j] += qf[i][2] * kf[j][2];
                    s[i][j] += qf[i][3] * kf[j][3];
                }
        }

        // + bias, online softmax
        #pragma unroll
        for (int i = 0; i < 4; i++) {
            const int r = q0 + 4 * ty + i;
            const float* brow = bias + (size_t)r * L_ + k0;
            #pragma unroll
            for (int j = 0; j < 4; j++)
                s[i][j] += __ldg(&brow[tx + 16 * j]);

            float mx = fmaxf(fmaxf(s[i][0], s[i][1]), fmaxf(s[i][2], s[i][3]));
            #pragma unroll
            for (int off = 8; off; off >>= 1)
                mx = fmaxf(mx, __shfl_xor_sync(0xffffffffu, mx, off, 16));
            const float mnew  = fmaxf(m_i[i], mx);
            const float alpha = __expf(m_i[i] - mnew);
            float rs = 0.f;
            #pragma unroll
            for (int j = 0; j < 4; j++) {
                s[i][j] = __expf(s[i][j] - mnew);
                rs += s[i][j];
            }
            #pragma unroll
            for (int off = 8; off; off >>= 1)
                rs += __shfl_xor_sync(0xffffffffu, rs, off, 16);
            l_i[i] = l_i[i] * alpha + rs;
            m_i[i] = mnew;
            #pragma unroll
            for (int d = 0; d < 4; d++) O[i][d] *= alpha;
            #pragma unroll
            for (int j = 0; j < 4; j++)
                Ps[(4 * ty + i) * 64 + tx + 16 * j] = s[i][j];
        }
        __syncthreads();

        // O += P @ V
        #pragma unroll 4
        for (int c = 0; c < 64; c += 4) {
            float pf[4][4], vf[4][4];
            #pragma unroll
            for (int i = 0; i < 4; i++)
                *(float4*)pf[i] = *(float4*)&Ps[(4 * ty + i) * 64 + c];
            #pragma unroll
            for (int cc = 0; cc < 4; cc++)
                *(float4*)vf[cc] = *(float4*)&Vs[(c + cc) * 68 + 4 * tx];
            #pragma unroll
            for (int i = 0; i < 4; i++)
                #pragma unroll
                for (int cc = 0; cc < 4; cc++) {
                    O[i][0] += pf[i][cc] * vf[cc][0];
                    O[i][1] += pf[i][cc] * vf[cc][1];
                    O[i][2] += pf[i][cc] * vf[cc][2];
                    O[i][3] += pf[i][cc] * vf[cc][3];
                }
        }
    }

    // epilogue: O /= l, write to g_ao[b][l][h*64 + d]
    const int b = bh >> 4;
    const int h = bh & 15;
    #pragma unroll
    for (int i = 0; i < 4; i++) {
        const float inv = 1.f / l_i[i];
        float4 o;
        o.x = O[i][0] * inv; o.y = O[i][1] * inv;
        o.z = O[i][2] * inv; o.w = O[i][3] * inv;
        const int l = q0 + 4 * ty + i;
        *(float4*)&g_ao[((size_t)b * L_ + l) * C_ + h * 64 + 4 * tx] = o;
    }
}

// ---------------------------------------------------------------------------
extern "C" void kernel_launch(void* const* d_in, const int* in_sizes, int n_in,
                              void* d_out, int out_size)
{
    (void)in_sizes; (void)n_in; (void)out_size;
    const float* x         = (const float*)d_in[0];
    const float* attn_bias = (const float*)d_in[1];
    const float* w_qkv     = (const float*)d_in[2];
    const float* q_bias    = (const float*)d_in[3];
    const float* v_bias    = (const float*)d_in[4];
    const float* scale_mul = (const float*)d_in[5];
    const float* w_proj    = (const float*)d_in[6];
    const float* b_proj    = (const float*)d_in[7];
    float* out = (float*)d_out;

    // 1) QKV projection: [4096,1024] x [3072,1024]^T
    gemm_kernel<0><<<dim3(NQKV_/128, M_/128), 256>>>(x, w_qkv, q_bias, v_bias, nullptr);

    // 2) L2 normalize q (with per-head scale) and k
    norm_kernel<<<(2 * B_ * H_ * L_) / 8, 256>>>(scale_mul);

    // 3) fused attention
    const int smem_bytes = (3 * 64 * 68 + 64 * 64) * (int)sizeof(float);  // 68608
    static int attr_done = 0;
    // attribute set is idempotent; safe during capture (not a stream op)
    cudaFuncSetAttribute(attn_kernel, cudaFuncAttributeMaxDynamicSharedMemorySize, smem_bytes);
    (void)attr_done;
    attn_kernel<<<dim3(L_/64, B_*H_), 256, smem_bytes>>>(attn_bias);

    // 4) output projection: [4096,1024] x [1024,1024]^T + b_proj
    gemm_kernel<1><<<dim3(C_/128, M_/128), 256>>>(nullptr, w_proj, b_proj, nullptr, out);
}